// round 1
// baseline (speedup 1.0000x reference)
#include <cuda_runtime.h>
#include <math.h>

// LSTM scan: B=256, T=512, D=1, H=512. W: [D+H, 4H] = [513, 2048], gates (i,j,f,o).
// c_new = c*sigmoid(f + 1.0) + sigmoid(i)*tanh(j);  h_new = tanh(c_new)*sigmoid(o)
// out: [B, T, H] fp32.

#define BATCH 256
#define TSTEPS 512
#define HDIM 512
#define GDIM 2048   // 4*H
#define WROWS 513   // D + H

// Persistent state (device globals — no allocation allowed).
__device__ float g_h[2][BATCH * HDIM];
__device__ float g_c[BATCH * HDIM];

__global__ void lstm_init() {
    int n = BATCH * HDIM;
    for (int i = blockIdx.x * blockDim.x + threadIdx.x; i < n;
         i += gridDim.x * blockDim.x) {
        g_h[0][i] = 0.0f;
        g_c[i] = 0.0f;
    }
}

__device__ __forceinline__ float sigmoidf_(float v) {
    return 1.0f / (1.0f + expf(-v));
}

// Tiles: BM=32 batch rows, BH=32 h-cols (=> 128 gate cols), BK=32.
// Grid: (HDIM/32, BATCH/32) = (16, 8) = 128 blocks, 256 threads each.
__global__ void __launch_bounds__(256, 1) lstm_step(
    const float* __restrict__ x,      // [B, T, 1]
    const float* __restrict__ W,      // [513, 2048] row-major
    const float* __restrict__ bias,   // [2048]
    float* __restrict__ out,          // [B, T, H]
    int t)
{
    const float* __restrict__ hprev = g_h[t & 1];
    float* __restrict__ hnext = g_h[(t + 1) & 1];

    __shared__ float as[32][32];    // h tile: [row][k]
    __shared__ float bs[32][128];   // W tile: [k][gatecol_local]
    __shared__ float zs[32][128];   // z staging for gate fusion

    const int tid = threadIdx.x;
    const int m_base = blockIdx.y * 32;   // batch row base
    const int n_base = blockIdx.x * 32;   // h-col base

    const int ty = tid >> 5;   // 0..7  -> rows ty*4 .. ty*4+3
    const int tx = tid & 31;   // 0..31 -> cols tx*4 .. tx*4+3

    float acc[4][4] = {};

    // ---- GEMM: z_tile += h_prev[m_base:+32, :] @ W[1:, gatecols] ----
    for (int k0 = 0; k0 < HDIM; k0 += 32) {
        // Load A: as[r][c] = hprev[(m_base+r)*H + k0+c]   (coalesced)
        #pragma unroll
        for (int i = 0; i < 4; i++) {
            int e = i * 256 + tid;
            int r = e >> 5, c = e & 31;
            as[r][c] = hprev[(m_base + r) * HDIM + k0 + c];
        }
        // Load B: local gate col j -> global col (j/32)*H + n_base + (j%32)
        #pragma unroll
        for (int i = 0; i < 16; i++) {
            int e = i * 256 + tid;
            int kr = e >> 7, j = e & 127;
            int gcol = ((j >> 5) * HDIM) + n_base + (j & 31);
            bs[kr][j] = W[(size_t)(1 + k0 + kr) * GDIM + gcol];
        }
        __syncthreads();

        #pragma unroll
        for (int k = 0; k < 32; k++) {
            float a0 = as[ty * 4 + 0][k];
            float a1 = as[ty * 4 + 1][k];
            float a2 = as[ty * 4 + 2][k];
            float a3 = as[ty * 4 + 3][k];
            float4 b4 = *(const float4*)&bs[k][tx * 4];
            acc[0][0] = fmaf(a0, b4.x, acc[0][0]);
            acc[0][1] = fmaf(a0, b4.y, acc[0][1]);
            acc[0][2] = fmaf(a0, b4.z, acc[0][2]);
            acc[0][3] = fmaf(a0, b4.w, acc[0][3]);
            acc[1][0] = fmaf(a1, b4.x, acc[1][0]);
            acc[1][1] = fmaf(a1, b4.y, acc[1][1]);
            acc[1][2] = fmaf(a1, b4.z, acc[1][2]);
            acc[1][3] = fmaf(a1, b4.w, acc[1][3]);
            acc[2][0] = fmaf(a2, b4.x, acc[2][0]);
            acc[2][1] = fmaf(a2, b4.y, acc[2][1]);
            acc[2][2] = fmaf(a2, b4.z, acc[2][2]);
            acc[2][3] = fmaf(a2, b4.w, acc[2][3]);
            acc[3][0] = fmaf(a3, b4.x, acc[3][0]);
            acc[3][1] = fmaf(a3, b4.y, acc[3][1]);
            acc[3][2] = fmaf(a3, b4.z, acc[3][2]);
            acc[3][3] = fmaf(a3, b4.w, acc[3][3]);
        }
        __syncthreads();
    }

    // Stage z to smem so each thread can gather its (i,j,f,o) quadruple.
    #pragma unroll
    for (int rr = 0; rr < 4; rr++)
        #pragma unroll
        for (int cc = 0; cc < 4; cc++)
            zs[ty * 4 + rr][tx * 4 + cc] = acc[rr][cc];
    __syncthreads();

    // ---- Gate fusion: each thread handles 4 (batch, hcol) outputs ----
    #pragma unroll
    for (int i = 0; i < 4; i++) {
        int o = i * 256 + tid;
        int r = o >> 5;          // local batch row
        int hc = o & 31;         // local h col
        int b_row = m_base + r;
        int h_col = n_base + hc;

        float xv = x[b_row * TSTEPS + t];   // D == 1

        // x contribution (W row 0) + bias, per gate
        float zi = zs[r][hc]      + fmaf(xv, W[0 * HDIM + h_col],           bias[0 * HDIM + h_col]);
        float zj = zs[r][32 + hc] + fmaf(xv, W[1 * HDIM + h_col],           bias[1 * HDIM + h_col]);
        float zf = zs[r][64 + hc] + fmaf(xv, W[2 * HDIM + h_col],           bias[2 * HDIM + h_col]);
        float zo = zs[r][96 + hc] + fmaf(xv, W[3 * HDIM + h_col],           bias[3 * HDIM + h_col]);

        int sidx = b_row * HDIM + h_col;
        float c_old = g_c[sidx];

        float fg = sigmoidf_(zf + 1.0f);          // FORGET_BIAS
        float ig = sigmoidf_(zi);
        float og = sigmoidf_(zo);
        float c_new = c_old * fg + ig * tanhf(zj);
        float h_new = tanhf(c_new) * og;

        g_c[sidx] = c_new;
        hnext[sidx] = h_new;
        out[(size_t)b_row * (TSTEPS * HDIM) + (size_t)t * HDIM + h_col] = h_new;
    }
}

extern "C" void kernel_launch(void* const* d_in, const int* in_sizes, int n_in,
                              void* d_out, int out_size) {
    const float* x    = (const float*)d_in[0];
    const float* W    = (const float*)d_in[1];
    const float* bias = (const float*)d_in[2];
    float* out = (float*)d_out;

    (void)in_sizes; (void)n_in; (void)out_size;

    lstm_init<<<256, 256>>>();

    dim3 grid(HDIM / 32, BATCH / 32);  // (16, 8) = 128 blocks
    for (int t = 0; t < TSTEPS; t++) {
        lstm_step<<<grid, 256>>>(x, W, bias, out, t);
    }
}